// round 11
// baseline (speedup 1.0000x reference)
#include <cuda_runtime.h>
#include <cuda_fp16.h>
#include <cstdint>
#include <math.h>

#define TOKENS 2048
#define HIDDEN 2048
#define INTER  1408
#define NEXP   8
#define KTH    64          // k elements per tile (halfs) = 128B rows
#define STAGES 3

#define AT_B    (64  * 144)        // A tile bytes  (9216)   row stride 144B
#define BT_B    (128 * 144)        // B tile bytes  (18432)
#define STAGE_B (AT_B + BT_B)      // 27648
#define SMEM_BYTES (256 + STAGES * STAGE_B)   // 83200

// ---------------- device scratch (no allocation) ----------------
__device__ int    g_counts[NEXP];
__device__ int    g_pairs[NEXP * TOKENS];                 // encoded (t<<1)|slot
__device__ float  g_wts[TOKENS * 2];                      // combine weight per (t,slot)
__device__ __half g_x_h[(size_t)TOKENS * HIDDEN];         // x in fp16
__device__ __half g_wg_h[(size_t)NEXP * HIDDEN * INTER];  // w_gate fp16, [e][n][k]
__device__ __half g_wu_h[(size_t)NEXP * HIDDEN * INTER];  // w_up   fp16, [e][n][k]
__device__ __half g_wd_h[(size_t)NEXP * INTER * HIDDEN];  // w_down fp16, [e][n][k]
__device__ __half g_hbuf_h[(size_t)TOKENS * 2 * INTER];   // gated intermediate fp16

// m16n8k16 fp16 MMA, fp32 accumulate (standard PTX, sm_80+)
__device__ __forceinline__ void mma_f16(float* c, const uint32_t* a,
                                        uint32_t b0, uint32_t b1) {
    asm volatile(
        "mma.sync.aligned.m16n8k16.row.col.f32.f16.f16.f32 "
        "{%0,%1,%2,%3}, {%4,%5,%6,%7}, {%8,%9}, {%0,%1,%2,%3};"
        : "+f"(c[0]), "+f"(c[1]), "+f"(c[2]), "+f"(c[3])
        : "r"(a[0]), "r"(a[1]), "r"(a[2]), "r"(a[3]), "r"(b0), "r"(b1));
}

// ldmatrix x4 (b16): 4 8x8 fp16 matrices
__device__ __forceinline__ void ldsm4(uint32_t* r, uint32_t addr) {
    asm volatile("ldmatrix.sync.aligned.m8n8.x4.shared.b16 {%0,%1,%2,%3}, [%4];"
        : "=r"(r[0]), "=r"(r[1]), "=r"(r[2]), "=r"(r[3]) : "r"(addr));
}

__device__ __forceinline__ void cp16(uint32_t dst, const void* src, int sz) {
    asm volatile("cp.async.cg.shared.global [%0], [%1], 16, %2;"
                 :: "r"(dst), "l"(src), "r"(sz) : "memory");
}
#define CP_COMMIT() asm volatile("cp.async.commit_group;" ::: "memory")
#define CP_WAIT1()  asm volatile("cp.async.wait_group 1;" ::: "memory")

__device__ __forceinline__ uint32_t hpack(float a, float b) {
    __half2 h = __floats2half2_rn(a, b);
    return *(uint32_t*)&h;
}

// ---------------- kernel 0: zero counters ----------------
__global__ void zero_counts_kernel() {
    if (threadIdx.x < NEXP) g_counts[threadIdx.x] = 0;
}

// ---------------- zero output (atomicAdd target) ----------------
__global__ __launch_bounds__(256) void zero_out_kernel(float* __restrict__ out)
{
    size_t i = ((size_t)blockIdx.x * blockDim.x + threadIdx.x) * 4;
    *(float4*)(out + i) = make_float4(0.f, 0.f, 0.f, 0.f);
}

// ---------------- preprocessing: transpose+convert weights to fp16 ----------------
// src [e][K][N] (n contiguous, fp32) -> dst [e][N][K] (k contiguous, fp16)
__global__ __launch_bounds__(256) void transpose_cvt_kernel(
    const float* __restrict__ src, int which, int K, int N)
{
    __half* dst = (which == 0) ? g_wg_h : (which == 1) ? g_wu_h : g_wd_h;
    __shared__ uint32_t tile[32][33];   // one fp16 value per slot (low 16 bits)
    const size_t eoff = (size_t)blockIdx.z * K * N;
    const int n0 = blockIdx.x * 32;
    const int k0 = blockIdx.y * 32;
    const int t  = threadIdx.x;
    {
        int kr  = t >> 3;
        int nc4 = (t & 7) * 4;
        float4 v = *(const float4*)(src + eoff + (size_t)(k0 + kr) * N + n0 + nc4);
        tile[kr][nc4 + 0] = (uint32_t)__half_as_ushort(__float2half_rn(v.x));
        tile[kr][nc4 + 1] = (uint32_t)__half_as_ushort(__float2half_rn(v.y));
        tile[kr][nc4 + 2] = (uint32_t)__half_as_ushort(__float2half_rn(v.z));
        tile[kr][nc4 + 3] = (uint32_t)__half_as_ushort(__float2half_rn(v.w));
    }
    __syncthreads();
    {
        int nr  = t >> 3;
        int kc4 = (t & 7) * 4;
        uint2 o;
        o.x = tile[kc4 + 0][nr] | (tile[kc4 + 1][nr] << 16);
        o.y = tile[kc4 + 2][nr] | (tile[kc4 + 3][nr] << 16);
        *(uint2*)(dst + eoff + (size_t)(n0 + nr) * K + k0 + kc4) = o;
    }
}

// x -> fp16 (layout unchanged)
__global__ __launch_bounds__(256) void cvt_x_kernel(const float* __restrict__ src)
{
    size_t i = ((size_t)blockIdx.x * blockDim.x + threadIdx.x) * 4;
    float4 v = *(const float4*)(src + i);
    uint2 o;
    o.x = hpack(v.x, v.y);
    o.y = hpack(v.z, v.w);
    *(uint2*)(g_x_h + i) = o;
}

// ---------------- kernel 1: router ----------------
__global__ __launch_bounds__(256) void router_kernel(
    const float* __restrict__ x, const float* __restrict__ wr)
{
    int t = blockIdx.x;
    __shared__ float red[256][NEXP];
    float acc[NEXP];
#pragma unroll
    for (int e = 0; e < NEXP; e++) acc[e] = 0.f;
    const float* xr = x + (size_t)t * HIDDEN;
    for (int h = threadIdx.x; h < HIDDEN; h += 256) {
        float xv = xr[h];
        const float* w = wr + (size_t)h * NEXP;
#pragma unroll
        for (int e = 0; e < NEXP; e++) acc[e] += xv * w[e];
    }
#pragma unroll
    for (int e = 0; e < NEXP; e++) red[threadIdx.x][e] = acc[e];
    __syncthreads();
    for (int s = 128; s > 0; s >>= 1) {
        if (threadIdx.x < s) {
#pragma unroll
            for (int e = 0; e < NEXP; e++)
                red[threadIdx.x][e] += red[threadIdx.x + s][e];
        }
        __syncthreads();
    }
    if (threadIdx.x == 0) {
        float l[NEXP];
#pragma unroll
        for (int e = 0; e < NEXP; e++) l[e] = red[0][e];
        int i0 = 0;
#pragma unroll
        for (int e = 1; e < NEXP; e++) if (l[e] > l[i0]) i0 = e;
        int i1 = -1;
#pragma unroll
        for (int e = 0; e < NEXP; e++) {
            if (e == i0) continue;
            if (i1 < 0 || l[e] > l[i1]) i1 = e;
        }
        float w0 = 1.f / (1.f + __expf(l[i1] - l[i0]));
        float w1 = 1.f - w0;
        int p0 = atomicAdd(&g_counts[i0], 1);
        g_pairs[i0 * TOKENS + p0] = (t << 1);
        int p1 = atomicAdd(&g_counts[i1], 1);
        g_pairs[i1 * TOKENS + p1] = (t << 1) | 1;
        g_wts[(t << 1)]     = w0;
        g_wts[(t << 1) | 1] = w1;
    }
}

// ---------------- kernel 2: grouped gate+up GEMM (fp16, 64m x 64n) ----------------
// grid: x = m-tile (fastest) so concurrent CTAs share the B tile via L2
__global__ __launch_bounds__(256, 2) void gateup_kernel()
{
    const int e   = blockIdx.z;
    const int cnt = g_counts[e];
    const int m0  = blockIdx.x * 64;
    if (m0 >= cnt) return;
    const int n0  = blockIdx.y * 64;

    extern __shared__ __align__(16) uint32_t dsm[];
    int* rows_sh = (int*)dsm;
    const uint32_t sb = (uint32_t)__cvta_generic_to_shared(dsm);

    const int tid  = threadIdx.x;
    const int wid  = tid >> 5;
    const int lane = tid & 31;
    const int gr   = lane >> 2;
    const int tg   = lane & 3;
    const int wm   = (wid & 1) * 32;   // warp m offset
    const int wn   = (wid >> 1) * 32;  // warp B-row offset

    if (tid < 64) {
        int m = m0 + tid;
        rows_sh[tid] = (m < cnt) ? g_pairs[e * TOKENS + m] : -1;
    }
    __syncthreads();

    const size_t eoff = (size_t)e * HIDDEN * INTER;

    // staging: A 2 chunks of 16B, B 4 chunks of 16B per thread (8 chunks/row)
    const __half* asrc[2];
    int  asz[2];
    uint32_t adst[2];   // byte offset within stage
#pragma unroll
    for (int i = 0; i < 2; i++) {
        int q  = tid + 256 * i;
        int m  = q >> 3;
        int c  = q & 7;
        int pr = rows_sh[m];
        asz[i]  = (pr >= 0) ? 16 : 0;
        asrc[i] = g_x_h + (size_t)((pr >= 0) ? (pr >> 1) : 0) * HIDDEN + c * 8;
        adst[i] = (uint32_t)(m * 144 + c * 16);
    }
    const __half* bsrc[4];
    uint32_t bdst[4];
#pragma unroll
    for (int i = 0; i < 4; i++) {
        int q    = tid + 256 * i;
        int r    = q >> 3;               // B tile row 0..127
        int c    = q & 7;
        int half = (r >> 4) & 1;         // 0 gate / 1 up (16-row granularity)
        int nn   = n0 + (r >> 5) * 16 + (r & 15);
        bsrc[i]  = (half ? g_wu_h : g_wg_h) + eoff + (size_t)nn * HIDDEN + c * 8;
        bdst[i]  = (uint32_t)(r * 144 + c * 16);
    }

    const int rlo  = lane & 15;
    const int kadd = (lane >> 4) * 8;

    float acc[2][4][4];
#pragma unroll
    for (int i = 0; i < 2; i++)
#pragma unroll
        for (int j = 0; j < 4; j++)
#pragma unroll
            for (int c = 0; c < 4; c++) acc[i][j][c] = 0.f;

    // prologue
#pragma unroll
    for (int s = 0; s < STAGES - 1; s++) {
        uint32_t ab = sb + 256 + s * STAGE_B;
        uint32_t bb = ab + AT_B;
        size_t ko = (size_t)s * KTH;
#pragma unroll
        for (int i = 0; i < 2; i++) cp16(ab + adst[i], asrc[i] + ko, asz[i]);
#pragma unroll
        for (int i = 0; i < 4; i++) cp16(bb + bdst[i], bsrc[i] + ko, 16);
        CP_COMMIT();
    }

    const int NT = HIDDEN / KTH;   // 32
    int rd = 0, wr = STAGES - 1;
    for (int kt = 0; kt < NT; kt++) {
        CP_WAIT1();
        __syncthreads();

        if (kt + STAGES - 1 < NT) {
            uint32_t ab = sb + 256 + wr * STAGE_B;
            uint32_t bb = ab + AT_B;
            size_t ko = (size_t)(kt + STAGES - 1) * KTH;
#pragma unroll
            for (int i = 0; i < 2; i++) cp16(ab + adst[i], asrc[i] + ko, asz[i]);
#pragma unroll
            for (int i = 0; i < 4; i++) cp16(bb + bdst[i], bsrc[i] + ko, 16);
        }
        CP_COMMIT();

        const uint32_t Ab = sb + 256 + rd * STAGE_B;
        const uint32_t Bb = Ab + AT_B;
#pragma unroll
        for (int ks = 0; ks < 4; ks++) {
            const int k = ks * 16;
            uint32_t a[2][4];
#pragma unroll
            for (int mi = 0; mi < 2; mi++)
                ldsm4(a[mi], Ab + (uint32_t)((wm + mi * 16 + rlo) * 144 + (k + kadd) * 2));
            uint32_t b0[4], b1[4];
            ldsm4(b0, Bb + (uint32_t)((wn + rlo)      * 144 + (k + kadd) * 2));
            ldsm4(b1, Bb + (uint32_t)((wn + 16 + rlo) * 144 + (k + kadd) * 2));
#pragma unroll
            for (int mi = 0; mi < 2; mi++) {
                mma_f16(acc[mi][0], a[mi], b0[0], b0[2]);
                mma_f16(acc[mi][1], a[mi], b0[1], b0[3]);
                mma_f16(acc[mi][2], a[mi], b1[0], b1[2]);
                mma_f16(acc[mi][3], a[mi], b1[1], b1[3]);
            }
        }
        rd = (rd == STAGES - 1) ? 0 : rd + 1;
        wr = (wr == STAGES - 1) ? 0 : wr + 1;
    }

    // epilogue: nj 0,1 = gate, nj 2,3 = up at same output cols; hbuf fp16
    const int colbase = n0 + (wid >> 1) * 16 + 2 * tg;
#pragma unroll
    for (int mi = 0; mi < 2; mi++) {
#pragma unroll
        for (int half = 0; half < 2; half++) {
            int row = wm + mi * 16 + gr + half * 8;
            int pr  = rows_sh[row];
            if (pr < 0) continue;
            float wt = g_wts[pr];
            __half* hrow = g_hbuf_h + (size_t)pr * INTER;
#pragma unroll
            for (int nj = 0; nj < 2; nj++) {
                float g0 = acc[mi][nj][half * 2 + 0];
                float g1 = acc[mi][nj][half * 2 + 1];
                float u0 = acc[mi][nj + 2][half * 2 + 0];
                float u1 = acc[mi][nj + 2][half * 2 + 1];
                float h0 = (g0 / (1.f + __expf(-g0))) * u0 * wt;
                float h1 = (g1 / (1.f + __expf(-g1))) * u1 * wt;
                *(uint32_t*)&hrow[colbase + nj * 8] = hpack(h0, h1);
            }
        }
    }
}

// ---------------- kernel 3: grouped down GEMM (fp16, 64m x 128n) ----------------
// grid: x = m-tile (fastest). Epilogue atomicAdds directly into out[t][h]:
// exactly two contributions per element (slot 0/1); IEEE add is commutative,
// so the result is bitwise deterministic regardless of arrival order.
__global__ __launch_bounds__(256, 2) void down_kernel(float* __restrict__ out)
{
    const int e   = blockIdx.z;
    const int cnt = g_counts[e];
    const int m0  = blockIdx.x * 64;
    if (m0 >= cnt) return;
    const int n0  = blockIdx.y * 128;

    extern __shared__ __align__(16) uint32_t dsm[];
    int* rows_sh = (int*)dsm;
    const uint32_t sb = (uint32_t)__cvta_generic_to_shared(dsm);

    const int tid  = threadIdx.x;
    const int wid  = tid >> 5;
    const int lane = tid & 31;
    const int gr   = lane >> 2;
    const int tg   = lane & 3;
    const int wm   = (wid & 1) * 32;
    const int wn   = (wid >> 1) * 32;

    if (tid < 64) {
        int m = m0 + tid;
        rows_sh[tid] = (m < cnt) ? g_pairs[e * TOKENS + m] : -1;
    }
    __syncthreads();

    const size_t eoff = (size_t)e * HIDDEN * INTER;

    const __half* asrc[2];
    int  asz[2];
    uint32_t adst[2];
#pragma unroll
    for (int i = 0; i < 2; i++) {
        int q  = tid + 256 * i;
        int m  = q >> 3;
        int c  = q & 7;
        int pr = rows_sh[m];
        asz[i]  = (pr >= 0) ? 16 : 0;
        asrc[i] = g_hbuf_h + (size_t)((pr >= 0) ? pr : 0) * INTER + c * 8;
        adst[i] = (uint32_t)(m * 144 + c * 16);
    }
    const __half* bsrc[4];
    uint32_t bdst[4];
#pragma unroll
    for (int i = 0; i < 4; i++) {
        int q   = tid + 256 * i;
        int r   = q >> 3;
        int c   = q & 7;
        bsrc[i] = g_wd_h + eoff + (size_t)(n0 + r) * INTER + c * 8;
        bdst[i] = (uint32_t)(r * 144 + c * 16);
    }

    const int rlo  = lane & 15;
    const int kadd = (lane >> 4) * 8;

    float acc[2][4][4];
#pragma unroll
    for (int i = 0; i < 2; i++)
#pragma unroll
        for (int j = 0; j < 4; j++)
#pragma unroll
            for (int c = 0; c < 4; c++) acc[i][j][c] = 0.f;

#pragma unroll
    for (int s = 0; s < STAGES - 1; s++) {
        uint32_t ab = sb + 256 + s * STAGE_B;
        uint32_t bb = ab + AT_B;
        size_t ko = (size_t)s * KTH;
#pragma unroll
        for (int i = 0; i < 2; i++) cp16(ab + adst[i], asrc[i] + ko, asz[i]);
#pragma unroll
        for (int i = 0; i < 4; i++) cp16(bb + bdst[i], bsrc[i] + ko, 16);
        CP_COMMIT();
    }

    const int NT = INTER / KTH;   // 22
    int rd = 0, wr = STAGES - 1;
    for (int kt = 0; kt < NT; kt++) {
        CP_WAIT1();
        __syncthreads();

        if (kt + STAGES - 1 < NT) {
            uint32_t ab = sb + 256 + wr * STAGE_B;
            uint32_t bb = ab + AT_B;
            size_t ko = (size_t)(kt + STAGES - 1) * KTH;
#pragma unroll
            for (int i = 0; i < 2; i++) cp16(ab + adst[i], asrc[i] + ko, asz[i]);
#pragma unroll
            for (int i = 0; i < 4; i++) cp16(bb + bdst[i], bsrc[i] + ko, 16);
        }
        CP_COMMIT();

        const uint32_t Ab = sb + 256 + rd * STAGE_B;
        const uint32_t Bb = Ab + AT_B;
#pragma unroll
        for (int ks = 0; ks < 4; ks++) {
            const int k = ks * 16;
            uint32_t a[2][4];
#pragma unroll
            for (int mi = 0; mi < 2; mi++)
                ldsm4(a[mi], Ab + (uint32_t)((wm + mi * 16 + rlo) * 144 + (k + kadd) * 2));
            uint32_t b0[4], b1[4];
            ldsm4(b0, Bb + (uint32_t)((wn + rlo)      * 144 + (k + kadd) * 2));
            ldsm4(b1, Bb + (uint32_t)((wn + 16 + rlo) * 144 + (k + kadd) * 2));
#pragma unroll
            for (int mi = 0; mi < 2; mi++) {
                mma_f16(acc[mi][0], a[mi], b0[0], b0[2]);
                mma_f16(acc[mi][1], a[mi], b0[1], b0[3]);
                mma_f16(acc[mi][2], a[mi], b1[0], b1[2]);
                mma_f16(acc[mi][3], a[mi], b1[1], b1[3]);
            }
        }
        rd = (rd == STAGES - 1) ? 0 : rd + 1;
        wr = (wr == STAGES - 1) ? 0 : wr + 1;
    }

    // fused combine: atomicAdd both slots directly into out
    const int colbase = n0 + wn + 2 * tg;
#pragma unroll
    for (int mi = 0; mi < 2; mi++) {
#pragma unroll
        for (int half = 0; half < 2; half++) {
            int row = wm + mi * 16 + gr + half * 8;
            int pr  = rows_sh[row];
            if (pr < 0) continue;
            float* orow = out + (size_t)(pr >> 1) * HIDDEN;
#pragma unroll
            for (int nj = 0; nj < 4; nj++) {
                atomicAdd(&orow[colbase + nj * 8 + 0], acc[mi][nj][half * 2 + 0]);
                atomicAdd(&orow[colbase + nj * 8 + 1], acc[mi][nj][half * 2 + 1]);
            }
        }
    }
}

// ---------------- launch ----------------
extern "C" void kernel_launch(void* const* d_in, const int* in_sizes, int n_in,
                              void* d_out, int out_size)
{
    const float* x  = (const float*)d_in[0];
    const float* wr = (const float*)d_in[1];
    const float* wg = (const float*)d_in[2];
    const float* wu = (const float*)d_in[3];
    const float* wd = (const float*)d_in[4];
    float* out = (float*)d_out;

    cudaFuncSetAttribute(gateup_kernel, cudaFuncAttributeMaxDynamicSharedMemorySize, SMEM_BYTES);
    cudaFuncSetAttribute(down_kernel,  cudaFuncAttributeMaxDynamicSharedMemorySize, SMEM_BYTES);

    zero_counts_kernel<<<1, 32>>>();
    zero_out_kernel<<<(TOKENS * HIDDEN) / (256 * 4), 256>>>(out);
    router_kernel<<<TOKENS, 256>>>(x, wr);

    // preprocessing: fp16 conversion + weight transpose to [e][n][k]
    cvt_x_kernel<<<(TOKENS * HIDDEN) / (256 * 4), 256>>>(x);
    transpose_cvt_kernel<<<dim3(INTER / 32, HIDDEN / 32, NEXP), 256>>>(wg, 0, HIDDEN, INTER);
    transpose_cvt_kernel<<<dim3(INTER / 32, HIDDEN / 32, NEXP), 256>>>(wu, 1, HIDDEN, INTER);
    transpose_cvt_kernel<<<dim3(HIDDEN / 32, INTER / 32, NEXP), 256>>>(wd, 2, INTER, HIDDEN);

    dim3 g1(TOKENS / 64, INTER / 64, NEXP);     // m fastest: L2 B-tile sharing
    gateup_kernel<<<g1, 256, SMEM_BYTES>>>();

    dim3 g2(TOKENS / 64, HIDDEN / 128, NEXP);   // m fastest
    down_kernel<<<g2, 256, SMEM_BYTES>>>(out);
}

// round 12
// speedup vs baseline: 1.0814x; 1.0814x over previous
#include <cuda_runtime.h>
#include <cuda_fp16.h>
#include <cstdint>
#include <math.h>

#define TOKENS 2048
#define HIDDEN 2048
#define INTER  1408
#define NEXP   8
#define KTH    64          // k elements per tile (halfs) = 128B of data per row
#define STAGES 3

// gateup tiles: A [64m][64k] stride 144B; Bg/Bu [64k][64n] stride 144B
#define AT_B      (64 * 144)               // 9216
#define BGU_B     (64 * 144)               // 9216 per gate/up tile
#define STAGE_GU  (AT_B + 2 * BGU_B)       // 27648
#define SMEM_GU   (256 + STAGES * STAGE_GU)   // 83200
// down tiles: A [64m][64k] stride 144B; B [64k][128n] stride 272B
#define BDN_B     (64 * 272)               // 17408
#define STAGE_DN  (AT_B + BDN_B)           // 26624
#define SMEM_DN   (256 + STAGES * STAGE_DN)   // 80128

// ---------------- device scratch (no allocation) ----------------
__device__ int    g_counts[NEXP];
__device__ int    g_pairs[NEXP * TOKENS];                 // encoded (t<<1)|slot
__device__ float  g_wts[TOKENS * 2];                      // combine weight per (t,slot)
__device__ __half g_x_h[(size_t)TOKENS * HIDDEN];         // x in fp16
__device__ __half g_wg_h[(size_t)NEXP * HIDDEN * INTER];  // w_gate fp16, [e][k][n]
__device__ __half g_wu_h[(size_t)NEXP * HIDDEN * INTER];  // w_up   fp16, [e][k][n]
__device__ __half g_wd_h[(size_t)NEXP * INTER * HIDDEN];  // w_down fp16, [e][k][n]
__device__ __half g_hbuf_h[(size_t)TOKENS * 2 * INTER];   // gated intermediate fp16

// m16n8k16 fp16 MMA, fp32 accumulate (standard PTX, sm_80+)
__device__ __forceinline__ void mma_f16(float* c, const uint32_t* a,
                                        uint32_t b0, uint32_t b1) {
    asm volatile(
        "mma.sync.aligned.m16n8k16.row.col.f32.f16.f16.f32 "
        "{%0,%1,%2,%3}, {%4,%5,%6,%7}, {%8,%9}, {%0,%1,%2,%3};"
        : "+f"(c[0]), "+f"(c[1]), "+f"(c[2]), "+f"(c[3])
        : "r"(a[0]), "r"(a[1]), "r"(a[2]), "r"(a[3]), "r"(b0), "r"(b1));
}

__device__ __forceinline__ void ldsm4(uint32_t* r, uint32_t addr) {
    asm volatile("ldmatrix.sync.aligned.m8n8.x4.shared.b16 {%0,%1,%2,%3}, [%4];"
        : "=r"(r[0]), "=r"(r[1]), "=r"(r[2]), "=r"(r[3]) : "r"(addr));
}
// transposed variant: stored [k][n] (n contiguous), yields col-major B fragment
__device__ __forceinline__ void ldsm4t(uint32_t* r, uint32_t addr) {
    asm volatile("ldmatrix.sync.aligned.m8n8.x4.trans.shared.b16 {%0,%1,%2,%3}, [%4];"
        : "=r"(r[0]), "=r"(r[1]), "=r"(r[2]), "=r"(r[3]) : "r"(addr));
}

__device__ __forceinline__ void cp16(uint32_t dst, const void* src, int sz) {
    asm volatile("cp.async.cg.shared.global [%0], [%1], 16, %2;"
                 :: "r"(dst), "l"(src), "r"(sz) : "memory");
}
#define CP_COMMIT() asm volatile("cp.async.commit_group;" ::: "memory")
#define CP_WAIT1()  asm volatile("cp.async.wait_group 1;" ::: "memory")

__device__ __forceinline__ uint32_t hpack(float a, float b) {
    __half2 h = __floats2half2_rn(a, b);
    return *(uint32_t*)&h;
}

// ---------------- zero output + counters ----------------
__global__ __launch_bounds__(256) void zero_out_kernel(float* __restrict__ out)
{
    if (blockIdx.x == 0 && threadIdx.x < NEXP) g_counts[threadIdx.x] = 0;
    size_t i = ((size_t)blockIdx.x * blockDim.x + threadIdx.x) * 4;
    *(float4*)(out + i) = make_float4(0.f, 0.f, 0.f, 0.f);
}

// ---------------- preprocessing: streaming fp32 -> fp16 convert (no transpose) ----------------
// blockIdx.y selects wg / wu / wd. 8 elems per thread.
__global__ __launch_bounds__(256) void convert_w_kernel(
    const float* __restrict__ wg, const float* __restrict__ wu,
    const float* __restrict__ wd)
{
    const int which = blockIdx.y;
    const float* src = (which == 0) ? wg : (which == 1) ? wu : wd;
    __half* dst = (which == 0) ? g_wg_h : (which == 1) ? g_wu_h : g_wd_h;
    size_t i = ((size_t)blockIdx.x * 256 + threadIdx.x) * 8;
    float4 v0 = *(const float4*)(src + i);
    float4 v1 = *(const float4*)(src + i + 4);
    uint4 o;
    o.x = hpack(v0.x, v0.y);
    o.y = hpack(v0.z, v0.w);
    o.z = hpack(v1.x, v1.y);
    o.w = hpack(v1.z, v1.w);
    *(uint4*)(dst + i) = o;
}

// ---------------- kernel 1: router (also emits x in fp16) ----------------
__global__ __launch_bounds__(256) void router_kernel(
    const float* __restrict__ x, const float* __restrict__ wr)
{
    int t = blockIdx.x;
    __shared__ float red[256][NEXP];
    float acc[NEXP];
#pragma unroll
    for (int e = 0; e < NEXP; e++) acc[e] = 0.f;
    const float* xr = x + (size_t)t * HIDDEN;
    __half* xh = g_x_h + (size_t)t * HIDDEN;
    for (int h = threadIdx.x; h < HIDDEN; h += 256) {
        float xv = xr[h];
        xh[h] = __float2half_rn(xv);
        const float* w = wr + (size_t)h * NEXP;
#pragma unroll
        for (int e = 0; e < NEXP; e++) acc[e] += xv * w[e];
    }
#pragma unroll
    for (int e = 0; e < NEXP; e++) red[threadIdx.x][e] = acc[e];
    __syncthreads();
    for (int s = 128; s > 0; s >>= 1) {
        if (threadIdx.x < s) {
#pragma unroll
            for (int e = 0; e < NEXP; e++)
                red[threadIdx.x][e] += red[threadIdx.x + s][e];
        }
        __syncthreads();
    }
    if (threadIdx.x == 0) {
        float l[NEXP];
#pragma unroll
        for (int e = 0; e < NEXP; e++) l[e] = red[0][e];
        int i0 = 0;
#pragma unroll
        for (int e = 1; e < NEXP; e++) if (l[e] > l[i0]) i0 = e;
        int i1 = -1;
#pragma unroll
        for (int e = 0; e < NEXP; e++) {
            if (e == i0) continue;
            if (i1 < 0 || l[e] > l[i1]) i1 = e;
        }
        float w0 = 1.f / (1.f + __expf(l[i1] - l[i0]));
        float w1 = 1.f - w0;
        int p0 = atomicAdd(&g_counts[i0], 1);
        g_pairs[i0 * TOKENS + p0] = (t << 1);
        int p1 = atomicAdd(&g_counts[i1], 1);
        g_pairs[i1 * TOKENS + p1] = (t << 1) | 1;
        g_wts[(t << 1)]     = w0;
        g_wts[(t << 1) | 1] = w1;
    }
}

// ---------------- kernel 2: grouped gate+up GEMM (fp16, 64m x 64n, ldmatrix.trans B) ----------------
__global__ __launch_bounds__(256, 2) void gateup_kernel()
{
    const int e   = blockIdx.z;
    const int cnt = g_counts[e];
    const int m0  = blockIdx.x * 64;
    if (m0 >= cnt) return;
    const int n0  = blockIdx.y * 64;

    extern __shared__ __align__(16) uint32_t dsm[];
    int* rows_sh = (int*)dsm;
    const uint32_t sb = (uint32_t)__cvta_generic_to_shared(dsm);

    const int tid  = threadIdx.x;
    const int wid  = tid >> 5;
    const int lane = tid & 31;
    const int gr   = lane >> 2;
    const int tg   = lane & 3;
    const int wm   = (wid & 1) * 32;   // warp m offset
    const int wq   = (wid >> 1);       // warp n-quarter (16 cols)

    if (tid < 64) {
        int m = m0 + tid;
        rows_sh[tid] = (m < cnt) ? g_pairs[e * TOKENS + m] : -1;
    }
    __syncthreads();

    const size_t eoff = (size_t)e * HIDDEN * INTER;

    // ---- staging (per thread): A 2 chunks, Bg 2, Bu 2 of 16B ----
    const __half* asrc[2];
    int  asz[2];
    uint32_t adst[2];
#pragma unroll
    for (int i = 0; i < 2; i++) {
        int q  = tid + 256 * i;
        int m  = q >> 3;
        int c  = q & 7;
        int pr = rows_sh[m];
        asz[i]  = (pr >= 0) ? 16 : 0;
        asrc[i] = g_x_h + (size_t)((pr >= 0) ? (pr >> 1) : 0) * HIDDEN + c * 8;
        adst[i] = (uint32_t)(m * 144 + c * 16);
    }
    // B tiles: rows = k (n contiguous in global!)
    const __half* bgsrc[2];
    const __half* busrc[2];
    uint32_t bdst[2];
#pragma unroll
    for (int i = 0; i < 2; i++) {
        int q  = tid + 256 * i;
        int kr = q >> 3;
        int c  = q & 7;
        bgsrc[i] = g_wg_h + eoff + (size_t)kr * INTER + n0 + c * 8;
        busrc[i] = g_wu_h + eoff + (size_t)kr * INTER + n0 + c * 8;
        bdst[i]  = (uint32_t)(kr * 144 + c * 16);
    }

    // ldmatrix lane constants
    const int rlo    = lane & 15;                       // A rows
    const int kadd   = (lane >> 4) * 8;                 // A col half
    const int krow_l = ((lane >> 4) << 3) + (lane & 7); // B k-row (trans)
    const int bcol_b = (wq * 16 + ((lane >> 3) & 1) * 8) * 2; // B col bytes

    float acc[2][4][4];
#pragma unroll
    for (int i = 0; i < 2; i++)
#pragma unroll
        for (int j = 0; j < 4; j++)
#pragma unroll
            for (int c = 0; c < 4; c++) acc[i][j][c] = 0.f;

    // prologue
#pragma unroll
    for (int s = 0; s < STAGES - 1; s++) {
        uint32_t ab = sb + 256 + s * STAGE_GU;
        uint32_t gb = ab + AT_B;
        uint32_t ub = gb + BGU_B;
        size_t koA = (size_t)s * KTH;
        size_t koB = (size_t)s * KTH * INTER;
#pragma unroll
        for (int i = 0; i < 2; i++) {
            cp16(ab + adst[i], asrc[i] + koA, asz[i]);
            cp16(gb + bdst[i], bgsrc[i] + koB, 16);
            cp16(ub + bdst[i], busrc[i] + koB, 16);
        }
        CP_COMMIT();
    }

    const int NT = HIDDEN / KTH;   // 32
    int rd = 0, wr = STAGES - 1;
    for (int kt = 0; kt < NT; kt++) {
        CP_WAIT1();
        __syncthreads();

        if (kt + STAGES - 1 < NT) {
            uint32_t ab = sb + 256 + wr * STAGE_GU;
            uint32_t gb = ab + AT_B;
            uint32_t ub = gb + BGU_B;
            size_t koA = (size_t)(kt + STAGES - 1) * KTH;
            size_t koB = koA * INTER;
#pragma unroll
            for (int i = 0; i < 2; i++) {
                cp16(ab + adst[i], asrc[i] + koA, asz[i]);
                cp16(gb + bdst[i], bgsrc[i] + koB, 16);
                cp16(ub + bdst[i], busrc[i] + koB, 16);
            }
        }
        CP_COMMIT();

        const uint32_t Ab = sb + 256 + rd * STAGE_GU;
        const uint32_t Gb = Ab + AT_B;
        const uint32_t Ub = Gb + BGU_B;
#pragma unroll
        for (int ks = 0; ks < 4; ks++) {
            const int k = ks * 16;
            uint32_t a[2][4];
#pragma unroll
            for (int mi = 0; mi < 2; mi++)
                ldsm4(a[mi], Ab + (uint32_t)((wm + mi * 16 + rlo) * 144 + (k + kadd) * 2));
            uint32_t b0[4], b1[4];
            ldsm4t(b0, Gb + (uint32_t)((k + krow_l) * 144) + bcol_b);
            ldsm4t(b1, Ub + (uint32_t)((k + krow_l) * 144) + bcol_b);
#pragma unroll
            for (int mi = 0; mi < 2; mi++) {
                mma_f16(acc[mi][0], a[mi], b0[0], b0[2]);   // gate n[0,8)
                mma_f16(acc[mi][1], a[mi], b0[1], b0[3]);   // gate n[8,16)
                mma_f16(acc[mi][2], a[mi], b1[0], b1[2]);   // up   n[0,8)
                mma_f16(acc[mi][3], a[mi], b1[1], b1[3]);   // up   n[8,16)
            }
        }
        rd = (rd == STAGES - 1) ? 0 : rd + 1;
        wr = (wr == STAGES - 1) ? 0 : wr + 1;
    }

    // epilogue: silu(gate)*up*wt -> hbuf fp16 (nj 0,1 gate; 2,3 up at same cols)
    const int colbase = n0 + wq * 16 + 2 * tg;
#pragma unroll
    for (int mi = 0; mi < 2; mi++) {
#pragma unroll
        for (int half = 0; half < 2; half++) {
            int row = wm + mi * 16 + gr + half * 8;
            int pr  = rows_sh[row];
            if (pr < 0) continue;
            float wt = g_wts[pr];
            __half* hrow = g_hbuf_h + (size_t)pr * INTER;
#pragma unroll
            for (int nj = 0; nj < 2; nj++) {
                float g0 = acc[mi][nj][half * 2 + 0];
                float g1 = acc[mi][nj][half * 2 + 1];
                float u0 = acc[mi][nj + 2][half * 2 + 0];
                float u1 = acc[mi][nj + 2][half * 2 + 1];
                float h0 = (g0 / (1.f + __expf(-g0))) * u0 * wt;
                float h1 = (g1 / (1.f + __expf(-g1))) * u1 * wt;
                *(uint32_t*)&hrow[colbase + nj * 8] = hpack(h0, h1);
            }
        }
    }
}

// ---------------- kernel 3: grouped down GEMM (fp16, 64m x 128n, ldmatrix.trans B) ----------------
__global__ __launch_bounds__(256, 2) void down_kernel(float* __restrict__ out)
{
    const int e   = blockIdx.z;
    const int cnt = g_counts[e];
    const int m0  = blockIdx.x * 64;
    if (m0 >= cnt) return;
    const int n0  = blockIdx.y * 128;

    extern __shared__ __align__(16) uint32_t dsm[];
    int* rows_sh = (int*)dsm;
    const uint32_t sb = (uint32_t)__cvta_generic_to_shared(dsm);

    const int tid  = threadIdx.x;
    const int wid  = tid >> 5;
    const int lane = tid & 31;
    const int gr   = lane >> 2;
    const int tg   = lane & 3;
    const int wm   = (wid & 1) * 32;
    const int wn   = (wid >> 1) * 32;

    if (tid < 64) {
        int m = m0 + tid;
        rows_sh[tid] = (m < cnt) ? g_pairs[e * TOKENS + m] : -1;
    }
    __syncthreads();

    const size_t eoff = (size_t)e * HIDDEN * INTER;

    const __half* asrc[2];
    int  asz[2];
    uint32_t adst[2];
#pragma unroll
    for (int i = 0; i < 2; i++) {
        int q  = tid + 256 * i;
        int m  = q >> 3;
        int c  = q & 7;
        int pr = rows_sh[m];
        asz[i]  = (pr >= 0) ? 16 : 0;
        asrc[i] = g_hbuf_h + (size_t)((pr >= 0) ? pr : 0) * INTER + c * 8;
        adst[i] = (uint32_t)(m * 144 + c * 16);
    }
    // B tile [64 k][128 n], rows = k (n contiguous in global), stride 272B
    const __half* bsrc[4];
    uint32_t bdst[4];
#pragma unroll
    for (int i = 0; i < 4; i++) {
        int q  = tid + 256 * i;
        int kr = q >> 4;
        int c  = q & 15;
        bsrc[i] = g_wd_h + eoff + (size_t)kr * HIDDEN + n0 + c * 8;
        bdst[i] = (uint32_t)(kr * 272 + c * 16);
    }

    const int rlo    = lane & 15;
    const int kadd   = (lane >> 4) * 8;
    const int krow_l = ((lane >> 4) << 3) + (lane & 7);
    const int bsel_b = (((lane >> 3) & 1) * 8) * 2;

    float acc[2][4][4];
#pragma unroll
    for (int i = 0; i < 2; i++)
#pragma unroll
        for (int j = 0; j < 4; j++)
#pragma unroll
            for (int c = 0; c < 4; c++) acc[i][j][c] = 0.f;

#pragma unroll
    for (int s = 0; s < STAGES - 1; s++) {
        uint32_t ab = sb + 256 + s * STAGE_DN;
        uint32_t bb = ab + AT_B;
        size_t koA = (size_t)s * KTH;
        size_t koB = (size_t)s * KTH * HIDDEN;
#pragma unroll
        for (int i = 0; i < 2; i++) cp16(ab + adst[i], asrc[i] + koA, asz[i]);
#pragma unroll
        for (int i = 0; i < 4; i++) cp16(bb + bdst[i], bsrc[i] + koB, 16);
        CP_COMMIT();
    }

    const int NT = INTER / KTH;   // 22
    int rd = 0, wr = STAGES - 1;
    for (int kt = 0; kt < NT; kt++) {
        CP_WAIT1();
        __syncthreads();

        if (kt + STAGES - 1 < NT) {
            uint32_t ab = sb + 256 + wr * STAGE_DN;
            uint32_t bb = ab + AT_B;
            size_t koA = (size_t)(kt + STAGES - 1) * KTH;
            size_t koB = koA * HIDDEN;
#pragma unroll
            for (int i = 0; i < 2; i++) cp16(ab + adst[i], asrc[i] + koA, asz[i]);
#pragma unroll
            for (int i = 0; i < 4; i++) cp16(bb + bdst[i], bsrc[i] + koB, 16);
        }
        CP_COMMIT();

        const uint32_t Ab = sb + 256 + rd * STAGE_DN;
        const uint32_t Bb = Ab + AT_B;
#pragma unroll
        for (int ks = 0; ks < 4; ks++) {
            const int k = ks * 16;
            uint32_t a[2][4];
#pragma unroll
            for (int mi = 0; mi < 2; mi++)
                ldsm4(a[mi], Ab + (uint32_t)((wm + mi * 16 + rlo) * 144 + (k + kadd) * 2));
            uint32_t b0[4], b1[4];
            ldsm4t(b0, Bb + (uint32_t)((k + krow_l) * 272 + wn * 2) + bsel_b);
            ldsm4t(b1, Bb + (uint32_t)((k + krow_l) * 272 + (wn + 16) * 2) + bsel_b);
#pragma unroll
            for (int mi = 0; mi < 2; mi++) {
                mma_f16(acc[mi][0], a[mi], b0[0], b0[2]);
                mma_f16(acc[mi][1], a[mi], b0[1], b0[3]);
                mma_f16(acc[mi][2], a[mi], b1[0], b1[2]);
                mma_f16(acc[mi][3], a[mi], b1[1], b1[3]);
            }
        }
        rd = (rd == STAGES - 1) ? 0 : rd + 1;
        wr = (wr == STAGES - 1) ? 0 : wr + 1;
    }

    // fused combine: atomicAdd both slots into out (2 adds/elem, commutative => deterministic)
    const int colbase = n0 + wn + 2 * tg;
#pragma unroll
    for (int mi = 0; mi < 2; mi++) {
#pragma unroll
        for (int half = 0; half < 2; half++) {
            int row = wm + mi * 16 + gr + half * 8;
            int pr  = rows_sh[row];
            if (pr < 0) continue;
            float* orow = out + (size_t)(pr >> 1) * HIDDEN;
#pragma unroll
            for (int nj = 0; nj < 4; nj++) {
                atomicAdd(&orow[colbase + nj * 8 + 0], acc[mi][nj][half * 2 + 0]);
                atomicAdd(&orow[colbase + nj * 8 + 1], acc[mi][nj][half * 2 + 1]);
            }
        }
    }
}

// ---------------- launch ----------------
extern "C" void kernel_launch(void* const* d_in, const int* in_sizes, int n_in,
                              void* d_out, int out_size)
{
    const float* x  = (const float*)d_in[0];
    const float* wr = (const float*)d_in[1];
    const float* wg = (const float*)d_in[2];
    const float* wu = (const float*)d_in[3];
    const float* wd = (const float*)d_in[4];
    float* out = (float*)d_out;

    cudaFuncSetAttribute(gateup_kernel, cudaFuncAttributeMaxDynamicSharedMemorySize, SMEM_GU);
    cudaFuncSetAttribute(down_kernel,  cudaFuncAttributeMaxDynamicSharedMemorySize, SMEM_DN);

    zero_out_kernel<<<(TOKENS * HIDDEN) / (256 * 4), 256>>>(out);
    router_kernel<<<TOKENS, 256>>>(x, wr);

    // streaming weight convert: 8 elems/thread, 3 arrays via blockIdx.y
    const int welems = NEXP * HIDDEN * INTER;                 // 23,068,672
    convert_w_kernel<<<dim3(welems / (256 * 8), 3), 256>>>(wg, wu, wd);

    dim3 g1(TOKENS / 64, INTER / 64, NEXP);     // m fastest: L2 B-tile sharing
    gateup_kernel<<<g1, 256, SMEM_GU>>>();

    dim3 g2(TOKENS / 64, HIDDEN / 128, NEXP);   // m fastest
    down_kernel<<<g2, 256, SMEM_DN>>>(out);
}